// round 16
// baseline (speedup 1.0000x reference)
#include <cuda_runtime.h>
#include <cuda_fp16.h>
#include <math.h>
#include <stdint.h>

// ---------------- problem constants ----------------
#define NC    8
#define HD    256
#define DIN   36
#define NMID  3
#define NMAX  65536
#define TM    64           // points per tile
#define NTHR  256          // 8 warps: 2 (m) x 4 (n)

#define BROW2     32       // chunk row stride bytes (16 fp16, XOR-swizzled -> conflict-free)
#define CHUNK2    8192     // 256 rows x 32B: one kstep of fp16 weights
#define NRING     8        // ring slots (power of 2)
#define GK        4        // ksteps per barrier group
#define NKSTEP    52       // 4 (layer0 K=64 padded) + 3*16 (mid layers K=256)
#define AROW      528      // A SMEM row stride bytes (33 x 16B, conflict-free ldmatrix)
#define HROW      264      // final fp32 hidden row stride (floats)

// SMEM layout (bytes)
#define SM_A     0                               // fp16 A image: 64 x 528 = 33792
#define SM_B     (SM_A + TM * AROW)              // 33792  (ring: 8 x 8192 = 65536)
#define SM_BIAS  (SM_B + NRING * CHUNK2)         // 99328  (4*256 floats)
#define SM_WOUT  (SM_BIAS + 4 * HD * 4)          // 103424 (3*256 floats)
#define SM_BOUT  (SM_WOUT + 3 * HD * 4)          // 106496 (4 floats)
#define SM_IDX   (SM_BOUT + 16)                  // 106512 (64 ints)
#define SMEM_BYTES (SM_IDX + TM * 4)             // 106768 (2 CTAs/SM)

// prep kernel block ranges
#define NB_SCAT  256
#define NB_MID   768      // 6144 mid rows / 8 warps
#define NB_WIN   256      // 2048 win rows / 8 warps
#define NB_WOUT  1
#define NB_PREP  (NB_SCAT + NB_MID + NB_WIN + NB_WOUT)

// ---------------- device scratch ----------------
__device__ float d_Wout[NC * NMID * HD];
__device__ __align__(512) unsigned char d_Wpk[NC * NKSTEP * CHUNK2];  // ~3.4 MB fp16 swizzled
__device__ int   d_sortedPad[NC * NMAX];
__device__ int   d_cursor[NC];
__device__ int   d_blkoff[NC + 1];

// swizzled in-chunk byte offset for (row r, k in [0,16))
__device__ __forceinline__ size_t wswz(int r, int k) {
    int k16 = (k >> 3) & 1;
    int sw  = k16 ^ ((r >> 2) & 1);
    return (size_t)r * BROW2 + (size_t)(sw << 4) + (size_t)(k & 7) * 2;
}

// ---------------- setup kernels ----------------
__global__ void initK() { if (threadIdx.x < NC) d_cursor[threadIdx.x] = 0; }

__global__ void prepK(const int* __restrict__ cid, int n,
                      const float* __restrict__ V_in,  const float* __restrict__ g_in,
                      const float* __restrict__ V_mid, const float* __restrict__ g_mid,
                      const float* __restrict__ V_out, const float* __restrict__ g_out) {
    const int blk  = blockIdx.x;
    const int tid  = threadIdx.x;
    const int wid  = tid >> 5;
    const int lane = tid & 31;

    if (blk < NB_SCAT) {
        __shared__ int lh[NC], base[NC];
        if (tid < NC) lh[tid] = 0;
        __syncthreads();
        int i = blk * 256 + tid;
        int c = -1, r = 0;
        if (i < n) { c = cid[i]; r = atomicAdd(&lh[c], 1); }
        __syncthreads();
        if (tid < NC) base[tid] = atomicAdd(&d_cursor[tid], lh[tid]);
        __syncthreads();
        if (i < n) d_sortedPad[c * NMAX + base[c] + r] = i;
        return;
    }
    if (blk < NB_SCAT + NB_MID) {
        // mid weights: norm + fp16 pack into swizzled chunks (ksteps 4..51)
        int row = (blk - NB_SCAT) * 8 + wid;         // [0, 6144)
        int c = row / (NMID * HD);
        int l = (row / HD) % NMID;
        int r = row & (HD - 1);
        const float* v = V_mid + (size_t)row * HD;
        float vals[8];
        float s = 0.f;
        #pragma unroll
        for (int j = 0; j < 8; j++) { vals[j] = v[lane + 32 * j]; s = fmaf(vals[j], vals[j], s); }
        #pragma unroll
        for (int off = 16; off; off >>= 1) s += __shfl_xor_sync(0xffffffffu, s, off);
        float scale = g_mid[row] * rsqrtf(s);
        #pragma unroll
        for (int j = 0; j < 8; j++) {
            int k = lane + 32 * j;
            int ks = 4 + l * 16 + (k >> 4);
            size_t ba = (size_t)(c * NKSTEP + ks) * CHUNK2 + wswz(r, k & 15);
            *reinterpret_cast<__half*>(d_Wpk + ba) = __float2half(vals[j] * scale);
        }
        return;
    }
    if (blk < NB_SCAT + NB_MID + NB_WIN) {
        // layer-0 weights: norm + fp16 pack, K padded 36 -> 64 (kstep 3 stays zero)
        int row = (blk - NB_SCAT - NB_MID) * 8 + wid;   // [0, 2048)
        int c = row >> 8;
        int r = row & 255;
        const float* v = V_in + (size_t)row * DIN;
        float v0 = v[lane];
        float v1 = (lane < DIN - 32) ? v[32 + lane] : 0.f;
        float s = fmaf(v0, v0, v1 * v1);
        #pragma unroll
        for (int off = 16; off; off >>= 1) s += __shfl_xor_sync(0xffffffffu, s, off);
        float scale = g_in[row] * rsqrtf(s);
        #pragma unroll
        for (int half = 0; half < 2; half++) {
            int k = lane + 32 * half;
            if (k >= 48) continue;
            float w = (k < 32) ? v0 * scale : ((k < DIN) ? v1 * scale : 0.f);
            int ks = k >> 4;
            size_t ba = (size_t)(c * NKSTEP + ks) * CHUNK2 + wswz(r, k & 15);
            *reinterpret_cast<__half*>(d_Wpk + ba) = __float2half(w);
        }
        return;
    }
    {
        #pragma unroll
        for (int it = 0; it < 3; it++) {
            int row = wid * 3 + it;                    // [0, 24)
            const float* v = V_out + (size_t)row * HD;
            float vals[8];
            float s = 0.f;
            #pragma unroll
            for (int j = 0; j < 8; j++) { vals[j] = v[lane + 32 * j]; s = fmaf(vals[j], vals[j], s); }
            #pragma unroll
            for (int off = 16; off; off >>= 1) s += __shfl_xor_sync(0xffffffffu, s, off);
            float scale = g_out[row] * rsqrtf(s);
            #pragma unroll
            for (int j = 0; j < 8; j++) d_Wout[row * HD + lane + 32 * j] = vals[j] * scale;
        }
    }
}

__global__ void prefixK() {
    if (threadIdx.x == 0) {
        int bo = 0;
        for (int c = 0; c < NC; c++) {
            d_blkoff[c] = bo;
            bo += (d_cursor[c] + TM - 1) / TM;
        }
        d_blkoff[NC] = bo;
    }
}

// ---------------- PTX helpers ----------------
__device__ __forceinline__ void cp16(uint32_t s, const void* g) {
    asm volatile("cp.async.cg.shared.global [%0], [%1], 16;" :: "r"(s), "l"(g));
}
__device__ __forceinline__ void cp_commit()  { asm volatile("cp.async.commit_group;"); }
__device__ __forceinline__ void cp_wait0()   { asm volatile("cp.async.wait_group 0;" ::: "memory"); }

__device__ __forceinline__ void ldsm4(uint32_t& r0, uint32_t& r1, uint32_t& r2, uint32_t& r3, uint32_t a) {
    asm volatile("ldmatrix.sync.aligned.m8n8.x4.shared.b16 {%0,%1,%2,%3}, [%4];"
                 : "=r"(r0), "=r"(r1), "=r"(r2), "=r"(r3) : "r"(a));
}

__device__ __forceinline__ void mma16816f(float* d, const uint32_t* a, uint32_t b0, uint32_t b1) {
    asm volatile("mma.sync.aligned.m16n8k16.row.col.f32.f16.f16.f32 "
                 "{%0,%1,%2,%3}, {%4,%5,%6,%7}, {%8,%9}, {%0,%1,%2,%3};"
                 : "+f"(d[0]), "+f"(d[1]), "+f"(d[2]), "+f"(d[3])
                 : "r"(a[0]), "r"(a[1]), "r"(a[2]), "r"(a[3]), "r"(b0), "r"(b1));
}

__device__ __forceinline__ uint32_t pack_h2(float a, float b) {
    __half2 h2 = __floats2half2_rn(a, b);
    return *reinterpret_cast<uint32_t*>(&h2);
}

// ---------------- fused MLP: fp16 single-MMA, persistent CTAs over tiles ----------------
__global__ void __launch_bounds__(NTHR, 2)
mlpK(const float* __restrict__ X,
     const float* __restrict__ b_in,
     const float* __restrict__ b_mid,
     const float* __restrict__ b_out,
     float* __restrict__ out, int n) {
    extern __shared__ unsigned char smem[];

    const int tid  = threadIdx.x;
    const int wid  = tid >> 5;
    const int lane = tid & 31;
    const int gid  = lane >> 2;
    const int tig  = lane & 3;
    const int sel  = lane >> 3;
    const int r8   = lane & 7;
    const uint32_t sbase = (uint32_t)__cvta_generic_to_shared(smem);

    float* biasS = (float*)(smem + SM_BIAS);
    float* WoutS = (float*)(smem + SM_WOUT);
    float* boutS = (float*)(smem + SM_BOUT);
    int*   idxS  = (int*)  (smem + SM_IDX);

    // warp tiling: 2 (m) x 4 (n)
    const int m_base = (wid & 1) * 32;
    const int wn     = wid >> 1;
    const int n_base = wn * 64;

    uint32_t a_off[2];
    #pragma unroll
    for (int im = 0; im < 2; im++)
        a_off[im] = (uint32_t)((m_base + im * 16 + r8 + (sel & 1) * 8) * AROW + (sel >> 1) * 16);
    uint32_t bg_off[4];
    #pragma unroll
    for (int jg = 0; jg < 4; jg++) {
        int row = n_base + jg * 16 + (sel >> 1) * 8 + r8;
        int sw  = (sel & 1) ^ ((r8 >> 2) & 1);
        bg_off[jg] = (uint32_t)(row * BROW2 + sw * 16);
    }

    const int nblocks = d_blkoff[NC];

    // ---- persistent loop over tiles ----
    for (int b = blockIdx.x; b < nblocks; b += gridDim.x) {

        int c = 0;
        while (b >= d_blkoff[c + 1]) c++;
        const int start = (b - d_blkoff[c]) * TM;
        int cnt = d_cursor[c] - start;
        if (cnt > TM) cnt = TM;
        if (cnt < 0) cnt = 0;

        // barrier: previous tile's output epilogue reads of SMEM must complete
        // before this tile's staging/posenc rewrites it
        __syncthreads();

        // ---- stage biases / Wout / bout ----
        #pragma unroll
        for (int it = 0; it < 4; it++) {
            int s = tid + it * NTHR;            // [0,1024)
            float v;
            if (s < HD) v = b_in[c * HD + s];
            else        v = b_mid[(c * NMID + (s / HD - 1)) * HD + (s & (HD - 1))];
            biasS[s] = v;
        }
        #pragma unroll
        for (int it = 0; it < 3; it++) {
            int s = tid + it * NTHR;
            WoutS[s] = d_Wout[c * NMID * HD + s];
        }
        if (tid < 3) boutS[tid] = b_out[c * NMID + tid];

        // ---- posenc -> fp16 A image (K padded to 64, cols 36..63 zero) ----
        if (tid < TM) {
            const int m = tid;
            const int id = (m < cnt) ? d_sortedPad[c * NMAX + start + m] : -1;
            idxS[m] = id;
            float e[36];
            #pragma unroll
            for (int k = 0; k < 36; k++) e[k] = 0.f;
            if (id >= 0) {
                float x = X[3 * id], y = X[3 * id + 1], z = X[3 * id + 2];
                float f = 1.f;
                #pragma unroll
                for (int fi = 0; fi < 6; fi++) {
                    float s0, c0, s1, c1, s2, c2;
                    sincosf(x * f, &s0, &c0);
                    sincosf(y * f, &s1, &c1);
                    sincosf(z * f, &s2, &c2);
                    e[fi * 6 + 0] = s0; e[fi * 6 + 1] = s1; e[fi * 6 + 2] = s2;
                    e[fi * 6 + 3] = c0; e[fi * 6 + 4] = c1; e[fi * 6 + 5] = c2;
                    f *= 2.f;
                }
            }
            uint32_t* arow = (uint32_t*)(smem + SM_A + m * AROW);
            #pragma unroll
            for (int i = 0; i < 18; i++) arow[i] = pack_h2(e[2 * i], e[2 * i + 1]);
            #pragma unroll
            for (int i = 18; i < 32; i++) arow[i] = 0u;
        }

        const unsigned char* wsrc = d_Wpk + (size_t)c * NKSTEP * CHUNK2;

        // prefetch group 0 (ksteps 0..3) into ring slots 0..3
        #pragma unroll
        for (int pc = 0; pc < GK; pc++) {
            const unsigned char* g = wsrc + (size_t)pc * CHUNK2;
            uint32_t sb = sbase + SM_B + pc * CHUNK2;
            #pragma unroll
            for (int j = 0; j < 2; j++) {
                int o = tid * 16 + j * 4096;
                cp16(sb + o, g + o);
            }
        }
        cp_commit();

        int q = 0;   // global kstep index

        #pragma unroll 1
        for (int l = 0; l < 4; l++) {
            float D[2][8][4];
            #pragma unroll
            for (int im = 0; im < 2; im++)
                #pragma unroll
                for (int jn = 0; jn < 8; jn++)
                    #pragma unroll
                    for (int e = 0; e < 4; e++) D[im][jn][e] = 0.f;

            const int nk = (l == 0) ? 4 : 16;
            #pragma unroll 1
            for (int t = 0; t < nk; t += GK) {
                // wait for current group's data; barrier protects ring reuse + A image
                cp_wait0();
                __syncthreads();

                // prefetch next group (ksteps q+GK .. q+2GK-1)
                #pragma unroll
                for (int pc = 0; pc < GK; pc++) {
                    int nq = q + GK + pc;
                    if (nq < NKSTEP) {
                        const unsigned char* g = wsrc + (size_t)nq * CHUNK2;
                        uint32_t sb = sbase + SM_B + (nq & (NRING - 1)) * CHUNK2;
                        #pragma unroll
                        for (int j = 0; j < 2; j++) {
                            int o = tid * 16 + j * 4096;
                            cp16(sb + o, g + o);
                        }
                    }
                }
                cp_commit();

                // ---- GK ksteps of MMA ----
                #pragma unroll
                for (int u = 0; u < GK; u++) {
                    const int qq = q + u;
                    const uint32_t kbA = (uint32_t)(t + u) * 32;
                    uint32_t A[2][4], Bf[4][4];
                    #pragma unroll
                    for (int im = 0; im < 2; im++)
                        ldsm4(A[im][0], A[im][1], A[im][2], A[im][3],
                              sbase + SM_A + a_off[im] + kbA);
                    const uint32_t bA = sbase + SM_B + (uint32_t)(qq & (NRING - 1)) * CHUNK2;
                    #pragma unroll
                    for (int jg = 0; jg < 4; jg++)
                        ldsm4(Bf[jg][0], Bf[jg][1], Bf[jg][2], Bf[jg][3], bA + bg_off[jg]);

                    #pragma unroll
                    for (int jg = 0; jg < 4; jg++)
                        #pragma unroll
                        for (int im = 0; im < 2; im++) {
                            mma16816f(D[im][jg * 2],     A[im], Bf[jg][0], Bf[jg][1]);
                            mma16816f(D[im][jg * 2 + 1], A[im], Bf[jg][2], Bf[jg][3]);
                        }
                }
                q += GK;
            }

            // ---- epilogue: barrier (all warps done reading A), rewrite A ----
            __syncthreads();
            const float* bias = biasS + l * HD;
            if (l < 3) {
                #pragma unroll
                for (int im = 0; im < 2; im++) {
                    #pragma unroll
                    for (int jn = 0; jn < 8; jn++) {
                        int ncol = n_base + jn * 8 + tig * 2;
                        float b0 = bias[ncol], b1 = bias[ncol + 1];
                        #pragma unroll
                        for (int h = 0; h < 2; h++) {
                            int m = m_base + im * 16 + gid + h * 8;
                            float v0 = fmaxf(D[im][jn][2 * h]     + b0, 0.f);
                            float v1 = fmaxf(D[im][jn][2 * h + 1] + b1, 0.f);
                            *(uint32_t*)(smem + SM_A + m * AROW + ncol * 2) = pack_h2(v0, v1);
                        }
                    }
                }
            } else {
                // final hidden -> fp32 h across A+ring region (HROW floats per row)
                float* hbuf = (float*)(smem + SM_A);
                #pragma unroll
                for (int im = 0; im < 2; im++) {
                    #pragma unroll
                    for (int jn = 0; jn < 8; jn++) {
                        int ncol = n_base + jn * 8 + tig * 2;
                        float b0 = bias[ncol], b1 = bias[ncol + 1];
                        #pragma unroll
                        for (int h = 0; h < 2; h++) {
                            int m = m_base + im * 16 + gid + h * 8;
                            float v0 = fmaxf(D[im][jn][2 * h]     + b0, 0.f);
                            float v1 = fmaxf(D[im][jn][2 * h + 1] + b1, 0.f);
                            float2* p = (float2*)(hbuf + m * HROW + ncol);
                            *p = make_float2(v0, v1);
                        }
                    }
                }
                __syncthreads();
                // fused output layer: 192 (m,j) dots of length 256
                const float* hb = (const float*)(smem + SM_A);
                #pragma unroll
                for (int qq = 0; qq < 24; qq++) {
                    int o = wid * 24 + qq;
                    int m = o / 3, j = o - 3 * m;
                    const float* hr = hb + m * HROW;
                    const float* wr = WoutS + j * HD;
                    float s = 0.f;
                    #pragma unroll
                    for (int k = lane; k < HD; k += 32) s = fmaf(hr[k], wr[k], s);
                    #pragma unroll
                    for (int off = 16; off; off >>= 1) s += __shfl_xor_sync(0xffffffffu, s, off);
                    if (lane == 0) {
                        int id = idxS[m];
                        if (id >= 0) out[3 * id + j] = tanhf(s + boutS[j]);
                    }
                }
            }
        }
    }
}

// ---------------- launch ----------------
extern "C" void kernel_launch(void* const* d_in, const int* in_sizes, int n_in,
                              void* d_out, int out_size) {
    const float* X     = (const float*)d_in[0];
    const int*   cid   = (const int*)  d_in[1];
    const float* V_in  = (const float*)d_in[2];
    const float* g_in  = (const float*)d_in[3];
    const float* b_in  = (const float*)d_in[4];
    const float* V_mid = (const float*)d_in[5];
    const float* g_mid = (const float*)d_in[6];
    const float* b_mid = (const float*)d_in[7];
    const float* V_out = (const float*)d_in[8];
    const float* g_out = (const float*)d_in[9];
    const float* b_out = (const float*)d_in[10];
    float* out = (float*)d_out;
    const int n = in_sizes[0] / 3;

    cudaFuncSetAttribute(mlpK, cudaFuncAttributeMaxDynamicSharedMemorySize, SMEM_BYTES);

    initK<<<1, 32>>>();
    prepK<<<NB_PREP, 256>>>(cid, n, V_in, g_in, V_mid, g_mid, V_out, g_out);
    prefixK<<<1, 1>>>();

    int sms = 148;
    cudaDeviceGetAttribute(&sms, cudaDevAttrMultiProcessorCount, 0);
    const int maxtiles = (n + TM - 1) / TM + NC;
    int np = 2 * sms;
    if (np > maxtiles) np = maxtiles;
    mlpK<<<np, NTHR, SMEM_BYTES>>>(X, b_in, b_mid, b_out, out, n);
}

// round 17
// speedup vs baseline: 1.0961x; 1.0961x over previous
#include <cuda_runtime.h>
#include <cuda_fp16.h>
#include <math.h>
#include <stdint.h>

// ---------------- problem constants ----------------
#define NC    8
#define HD    256
#define DIN   36
#define NMID  3
#define NMAX  65536
#define TM    64           // points per CTA
#define NTHR  256          // 8 warps: 2 (m) x 4 (n)

#define BROW2     32       // chunk row stride bytes (16 fp16, XOR-swizzled -> conflict-free)
#define CHUNK2    8192     // 256 rows x 32B: one kstep of fp16 weights
#define NRING     8        // ring slots (power of 2)
#define GK        4        // ksteps per barrier group
#define NKSTEP    52       // 4 (layer0 K=64 padded) + 3*16 (mid layers K=256)
#define AROW      528      // A SMEM row stride bytes (33 x 16B, conflict-free ldmatrix)
#define HROW      264      // final fp32 hidden row stride (floats)

// SMEM layout (bytes)
#define SM_A     0                               // fp16 A image: 64 x 528 = 33792
#define SM_B     (SM_A + TM * AROW)              // 33792  (ring: 8 x 8192 = 65536)
#define SM_BIAS  (SM_B + NRING * CHUNK2)         // 99328  (4*256 floats)
#define SM_WOUT  (SM_BIAS + 4 * HD * 4)          // 103424 (3*256 floats)
#define SM_BOUT  (SM_WOUT + 3 * HD * 4)          // 106496 (4 floats)
#define SM_IDX   (SM_BOUT + 16)                  // 106512 (64 ints)
#define SMEM_BYTES (SM_IDX + TM * 4)             // 106768 (2 CTAs/SM)

// prep kernel block ranges
#define NB_SCAT  256
#define NB_MID   768      // 6144 mid rows / 8 warps
#define NB_WIN   256      // 2048 win rows / 8 warps
#define NB_WOUT  1
#define NB_PREP  (NB_SCAT + NB_MID + NB_WIN + NB_WOUT)

// ---------------- device scratch ----------------
__device__ float d_Wout[NC * NMID * HD];
__device__ __align__(512) unsigned char d_Wpk[NC * NKSTEP * CHUNK2];  // ~3.4 MB fp16 swizzled
__device__ int   d_sortedPad[NC * NMAX];
__device__ int   d_cursor[NC];

// swizzled in-chunk byte offset for (row r, k in [0,16))
__device__ __forceinline__ size_t wswz(int r, int k) {
    int k16 = (k >> 3) & 1;
    int sw  = k16 ^ ((r >> 2) & 1);
    return (size_t)r * BROW2 + (size_t)(sw << 4) + (size_t)(k & 7) * 2;
}

// ---------------- setup kernels ----------------
__global__ void initK() { if (threadIdx.x < NC) d_cursor[threadIdx.x] = 0; }

__global__ void prepK(const int* __restrict__ cid, int n,
                      const float* __restrict__ V_in,  const float* __restrict__ g_in,
                      const float* __restrict__ V_mid, const float* __restrict__ g_mid,
                      const float* __restrict__ V_out, const float* __restrict__ g_out) {
    const int blk  = blockIdx.x;
    const int tid  = threadIdx.x;
    const int wid  = tid >> 5;
    const int lane = tid & 31;

    if (blk < NB_SCAT) {
        __shared__ int lh[NC], base[NC];
        if (tid < NC) lh[tid] = 0;
        __syncthreads();
        int i = blk * 256 + tid;
        int c = -1, r = 0;
        if (i < n) { c = cid[i]; r = atomicAdd(&lh[c], 1); }
        __syncthreads();
        if (tid < NC) base[tid] = atomicAdd(&d_cursor[tid], lh[tid]);
        __syncthreads();
        if (i < n) d_sortedPad[c * NMAX + base[c] + r] = i;
        return;
    }
    if (blk < NB_SCAT + NB_MID) {
        // mid weights: norm + fp16 pack into swizzled chunks (ksteps 4..51)
        int row = (blk - NB_SCAT) * 8 + wid;         // [0, 6144)
        int c = row / (NMID * HD);
        int l = (row / HD) % NMID;
        int r = row & (HD - 1);
        const float* v = V_mid + (size_t)row * HD;
        float vals[8];
        float s = 0.f;
        #pragma unroll
        for (int j = 0; j < 8; j++) { vals[j] = v[lane + 32 * j]; s = fmaf(vals[j], vals[j], s); }
        #pragma unroll
        for (int off = 16; off; off >>= 1) s += __shfl_xor_sync(0xffffffffu, s, off);
        float scale = g_mid[row] * rsqrtf(s);
        #pragma unroll
        for (int j = 0; j < 8; j++) {
            int k = lane + 32 * j;
            int ks = 4 + l * 16 + (k >> 4);
            size_t ba = (size_t)(c * NKSTEP + ks) * CHUNK2 + wswz(r, k & 15);
            *reinterpret_cast<__half*>(d_Wpk + ba) = __float2half(vals[j] * scale);
        }
        return;
    }
    if (blk < NB_SCAT + NB_MID + NB_WIN) {
        // layer-0 weights: norm + fp16 pack, K padded 36 -> 64 (kstep 3 stays zero)
        int row = (blk - NB_SCAT - NB_MID) * 8 + wid;   // [0, 2048)
        int c = row >> 8;
        int r = row & 255;
        const float* v = V_in + (size_t)row * DIN;
        float v0 = v[lane];
        float v1 = (lane < DIN - 32) ? v[32 + lane] : 0.f;
        float s = fmaf(v0, v0, v1 * v1);
        #pragma unroll
        for (int off = 16; off; off >>= 1) s += __shfl_xor_sync(0xffffffffu, s, off);
        float scale = g_in[row] * rsqrtf(s);
        #pragma unroll
        for (int half = 0; half < 2; half++) {
            int k = lane + 32 * half;
            if (k >= 48) continue;
            float w = (k < 32) ? v0 * scale : ((k < DIN) ? v1 * scale : 0.f);
            int ks = k >> 4;
            size_t ba = (size_t)(c * NKSTEP + ks) * CHUNK2 + wswz(r, k & 15);
            *reinterpret_cast<__half*>(d_Wpk + ba) = __float2half(w);
        }
        return;
    }
    {
        #pragma unroll
        for (int it = 0; it < 3; it++) {
            int row = wid * 3 + it;                    // [0, 24)
            const float* v = V_out + (size_t)row * HD;
            float vals[8];
            float s = 0.f;
            #pragma unroll
            for (int j = 0; j < 8; j++) { vals[j] = v[lane + 32 * j]; s = fmaf(vals[j], vals[j], s); }
            #pragma unroll
            for (int off = 16; off; off >>= 1) s += __shfl_xor_sync(0xffffffffu, s, off);
            float scale = g_out[row] * rsqrtf(s);
            #pragma unroll
            for (int j = 0; j < 8; j++) d_Wout[row * HD + lane + 32 * j] = vals[j] * scale;
        }
    }
}

// ---------------- PTX helpers ----------------
__device__ __forceinline__ void cp16(uint32_t s, const void* g) {
    asm volatile("cp.async.cg.shared.global [%0], [%1], 16;" :: "r"(s), "l"(g));
}
__device__ __forceinline__ void cp_commit()  { asm volatile("cp.async.commit_group;"); }
__device__ __forceinline__ void cp_wait0()   { asm volatile("cp.async.wait_group 0;" ::: "memory"); }

__device__ __forceinline__ void ldsm4(uint32_t& r0, uint32_t& r1, uint32_t& r2, uint32_t& r3, uint32_t a) {
    asm volatile("ldmatrix.sync.aligned.m8n8.x4.shared.b16 {%0,%1,%2,%3}, [%4];"
                 : "=r"(r0), "=r"(r1), "=r"(r2), "=r"(r3) : "r"(a));
}

__device__ __forceinline__ void mma16816f(float* d, const uint32_t* a, uint32_t b0, uint32_t b1) {
    asm volatile("mma.sync.aligned.m16n8k16.row.col.f32.f16.f16.f32 "
                 "{%0,%1,%2,%3}, {%4,%5,%6,%7}, {%8,%9}, {%0,%1,%2,%3};"
                 : "+f"(d[0]), "+f"(d[1]), "+f"(d[2]), "+f"(d[3])
                 : "r"(a[0]), "r"(a[1]), "r"(a[2]), "r"(a[3]), "r"(b0), "r"(b1));
}

__device__ __forceinline__ uint32_t pack_h2(float a, float b) {
    __half2 h2 = __floats2half2_rn(a, b);
    return *reinterpret_cast<uint32_t*>(&h2);
}

// ---------------- fused MLP: fp16 single-MMA, 8-slot ring, barrier per 4 ksteps ----------------
__global__ void __launch_bounds__(NTHR, 2)
mlpK(const float* __restrict__ X,
     const float* __restrict__ b_in,
     const float* __restrict__ b_mid,
     const float* __restrict__ b_out,
     float* __restrict__ out, int n) {
    extern __shared__ unsigned char smem[];

    // ---- inline prefix: derive (cluster, start, cnt) from d_cursor (8 counts) ----
    const int b = blockIdx.x;
    int c = -1, start = 0, cnt = 0;
    {
        int bo = 0;
        #pragma unroll
        for (int cc = 0; cc < NC; cc++) {
            int count = d_cursor[cc];
            int tiles = (count + TM - 1) / TM;
            if (c < 0 && b < bo + tiles) {
                c = cc;
                start = (b - bo) * TM;
                cnt = count - start;
            }
            bo += tiles;
        }
    }
    if (c < 0) return;
    if (cnt > TM) cnt = TM;

    const int tid  = threadIdx.x;
    const int wid  = tid >> 5;
    const int lane = tid & 31;
    const int gid  = lane >> 2;
    const int tig  = lane & 3;
    const int sel  = lane >> 3;
    const int r8   = lane & 7;
    const uint32_t sbase = (uint32_t)__cvta_generic_to_shared(smem);

    float* biasS = (float*)(smem + SM_BIAS);
    float* WoutS = (float*)(smem + SM_WOUT);
    float* boutS = (float*)(smem + SM_BOUT);
    int*   idxS  = (int*)  (smem + SM_IDX);

    // ---- stage biases / Wout / bout ----
    #pragma unroll
    for (int it = 0; it < 4; it++) {
        int s = tid + it * NTHR;            // [0,1024)
        float v;
        if (s < HD) v = b_in[c * HD + s];
        else        v = b_mid[(c * NMID + (s / HD - 1)) * HD + (s & (HD - 1))];
        biasS[s] = v;
    }
    #pragma unroll
    for (int it = 0; it < 3; it++) {
        int s = tid + it * NTHR;
        WoutS[s] = d_Wout[c * NMID * HD + s];
    }
    if (tid < 3) boutS[tid] = b_out[c * NMID + tid];

    // ---- posenc -> fp16 A image (K padded to 64, cols 36..63 zero) ----
    if (tid < TM) {
        const int m = tid;
        const int id = (m < cnt) ? d_sortedPad[c * NMAX + start + m] : -1;
        idxS[m] = id;
        float e[36];
        #pragma unroll
        for (int k = 0; k < 36; k++) e[k] = 0.f;
        if (id >= 0) {
            float x = X[3 * id], y = X[3 * id + 1], z = X[3 * id + 2];
            float f = 1.f;
            #pragma unroll
            for (int fi = 0; fi < 6; fi++) {
                float s0, c0, s1, c1, s2, c2;
                sincosf(x * f, &s0, &c0);
                sincosf(y * f, &s1, &c1);
                sincosf(z * f, &s2, &c2);
                e[fi * 6 + 0] = s0; e[fi * 6 + 1] = s1; e[fi * 6 + 2] = s2;
                e[fi * 6 + 3] = c0; e[fi * 6 + 4] = c1; e[fi * 6 + 5] = c2;
                f *= 2.f;
            }
        }
        uint32_t* arow = (uint32_t*)(smem + SM_A + m * AROW);
        #pragma unroll
        for (int i = 0; i < 18; i++) arow[i] = pack_h2(e[2 * i], e[2 * i + 1]);
        #pragma unroll
        for (int i = 18; i < 32; i++) arow[i] = 0u;
    }

    // warp tiling: 2 (m) x 4 (n)
    const int m_base = (wid & 1) * 32;
    const int wn     = wid >> 1;
    const int n_base = wn * 64;

    uint32_t a_off[2];
    #pragma unroll
    for (int im = 0; im < 2; im++)
        a_off[im] = (uint32_t)((m_base + im * 16 + r8 + (sel & 1) * 8) * AROW + (sel >> 1) * 16);
    // B ldsm offsets with XOR swizzle on the 16B selector
    uint32_t bg_off[4];
    #pragma unroll
    for (int jg = 0; jg < 4; jg++) {
        int row = n_base + jg * 16 + (sel >> 1) * 8 + r8;
        int sw  = (sel & 1) ^ ((r8 >> 2) & 1);
        bg_off[jg] = (uint32_t)(row * BROW2 + sw * 16);
    }

    const unsigned char* wsrc = d_Wpk + (size_t)c * NKSTEP * CHUNK2;

    // prefetch group 0 (ksteps 0..3) into ring slots 0..3
    #pragma unroll
    for (int pc = 0; pc < GK; pc++) {
        const unsigned char* g = wsrc + (size_t)pc * CHUNK2;
        uint32_t sb = sbase + SM_B + pc * CHUNK2;
        #pragma unroll
        for (int j = 0; j < 2; j++) {
            int o = tid * 16 + j * 4096;
            cp16(sb + o, g + o);
        }
    }
    cp_commit();

    int q = 0;   // global kstep index

    #pragma unroll 1
    for (int l = 0; l < 4; l++) {
        float D[2][8][4];
        #pragma unroll
        for (int im = 0; im < 2; im++)
            #pragma unroll
            for (int jn = 0; jn < 8; jn++)
                #pragma unroll
                for (int e = 0; e < 4; e++) D[im][jn][e] = 0.f;

        const int nk = (l == 0) ? 4 : 16;
        #pragma unroll 1
        for (int t = 0; t < nk; t += GK) {
            // wait for current group's data; barrier protects ring reuse + A image
            cp_wait0();
            __syncthreads();

            // prefetch next group (ksteps q+GK .. q+2GK-1)
            #pragma unroll
            for (int pc = 0; pc < GK; pc++) {
                int nq = q + GK + pc;
                if (nq < NKSTEP) {
                    const unsigned char* g = wsrc + (size_t)nq * CHUNK2;
                    uint32_t sb = sbase + SM_B + (nq & (NRING - 1)) * CHUNK2;
                    #pragma unroll
                    for (int j = 0; j < 2; j++) {
                        int o = tid * 16 + j * 4096;
                        cp16(sb + o, g + o);
                    }
                }
            }
            cp_commit();

            // ---- GK ksteps of MMA ----
            #pragma unroll
            for (int u = 0; u < GK; u++) {
                const int qq = q + u;
                const uint32_t kbA = (uint32_t)(t + u) * 32;
                uint32_t A[2][4], Bf[4][4];
                #pragma unroll
                for (int im = 0; im < 2; im++)
                    ldsm4(A[im][0], A[im][1], A[im][2], A[im][3],
                          sbase + SM_A + a_off[im] + kbA);
                const uint32_t bA = sbase + SM_B + (uint32_t)(qq & (NRING - 1)) * CHUNK2;
                #pragma unroll
                for (int jg = 0; jg < 4; jg++)
                    ldsm4(Bf[jg][0], Bf[jg][1], Bf[jg][2], Bf[jg][3], bA + bg_off[jg]);

                #pragma unroll
                for (int jg = 0; jg < 4; jg++)
                    #pragma unroll
                    for (int im = 0; im < 2; im++) {
                        mma16816f(D[im][jg * 2],     A[im], Bf[jg][0], Bf[jg][1]);
                        mma16816f(D[im][jg * 2 + 1], A[im], Bf[jg][2], Bf[jg][3]);
                    }
            }
            q += GK;
        }

        // ---- epilogue: barrier (all warps done reading A), rewrite A ----
        __syncthreads();
        const float* bias = biasS + l * HD;
        if (l < 3) {
            #pragma unroll
            for (int im = 0; im < 2; im++) {
                #pragma unroll
                for (int jn = 0; jn < 8; jn++) {
                    int ncol = n_base + jn * 8 + tig * 2;
                    float b0 = bias[ncol], b1 = bias[ncol + 1];
                    #pragma unroll
                    for (int h = 0; h < 2; h++) {
                        int m = m_base + im * 16 + gid + h * 8;
                        float v0 = fmaxf(D[im][jn][2 * h]     + b0, 0.f);
                        float v1 = fmaxf(D[im][jn][2 * h + 1] + b1, 0.f);
                        *(uint32_t*)(smem + SM_A + m * AROW + ncol * 2) = pack_h2(v0, v1);
                    }
                }
            }
        } else {
            // final hidden -> fp32 h across A+ring region (HROW floats per row)
            float* hbuf = (float*)(smem + SM_A);
            #pragma unroll
            for (int im = 0; im < 2; im++) {
                #pragma unroll
                for (int jn = 0; jn < 8; jn++) {
                    int ncol = n_base + jn * 8 + tig * 2;
                    float b0 = bias[ncol], b1 = bias[ncol + 1];
                    #pragma unroll
                    for (int h = 0; h < 2; h++) {
                        int m = m_base + im * 16 + gid + h * 8;
                        float v0 = fmaxf(D[im][jn][2 * h]     + b0, 0.f);
                        float v1 = fmaxf(D[im][jn][2 * h + 1] + b1, 0.f);
                        float2* p = (float2*)(hbuf + m * HROW + ncol);
                        *p = make_float2(v0, v1);
                    }
                }
            }
            __syncthreads();
            // fused output layer: 192 (m,j) dots of length 256
            const float* hb = (const float*)(smem + SM_A);
            #pragma unroll
            for (int qq = 0; qq < 24; qq++) {
                int o = wid * 24 + qq;
                int m = o / 3, j = o - 3 * m;
                const float* hr = hb + m * HROW;
                const float* wr = WoutS + j * HD;
                float s = 0.f;
                #pragma unroll
                for (int k = lane; k < HD; k += 32) s = fmaf(hr[k], wr[k], s);
                #pragma unroll
                for (int off = 16; off; off >>= 1) s += __shfl_xor_sync(0xffffffffu, s, off);
                if (lane == 0) {
                    int id = idxS[m];
                    if (id >= 0) out[3 * id + j] = tanhf(s + boutS[j]);
                }
            }
        }
    }
}

// ---------------- launch ----------------
extern "C" void kernel_launch(void* const* d_in, const int* in_sizes, int n_in,
                              void* d_out, int out_size) {
    const float* X     = (const float*)d_in[0];
    const int*   cid   = (const int*)  d_in[1];
    const float* V_in  = (const float*)d_in[2];
    const float* g_in  = (const float*)d_in[3];
    const float* b_in  = (const float*)d_in[4];
    const float* V_mid = (const float*)d_in[5];
    const float* g_mid = (const float*)d_in[6];
    const float* b_mid = (const float*)d_in[7];
    const float* V_out = (const float*)d_in[8];
    const float* g_out = (const float*)d_in[9];
    const float* b_out = (const float*)d_in[10];
    float* out = (float*)d_out;
    const int n = in_sizes[0] / 3;

    cudaFuncSetAttribute(mlpK, cudaFuncAttributeMaxDynamicSharedMemorySize, SMEM_BYTES);

    initK<<<1, 32>>>();
    prepK<<<NB_PREP, 256>>>(cid, n, V_in, g_in, V_mid, g_mid, V_out, g_out);

    const int blocks = (n + TM - 1) / TM + NC;
    mlpK<<<blocks, NTHR, SMEM_BYTES>>>(X, b_in, b_mid, b_out, out, n);
}